// round 10
// baseline (speedup 1.0000x reference)
#include <cuda_runtime.h>
#include <cuda_fp16.h>

#define NF 512
#define NH 16
#define NC 40
#define NMAX 100000

// ---- scratch (static device globals; no allocations allowed) ----
__device__ float  g_deg[NMAX];
__device__ float  g_dinv[NMAX];
__device__ float  g_h1[NMAX * NH];    // x@W1+b1 (fp32, gemm output)
__device__ __half g_h1h[NMAX * NH];   // dinv*h1 in fp16 (gather source, 32B/row)
__device__ float  g_a1[NMAX * NH];    // layer-1 accumulator (init = dinv*h1 self term)
__device__ __half g_a1sh[NMAX * NH];  // dinv*relu(...) in fp16 (gather source)
__device__ float  g_agg2[NMAX * NH];  // layer-2 accumulator (init = a1s self term)
__device__ float  g_nsum[NMAX];       // bias weight accumulator (init = dinv self)

// packed fp32x2 FMA (Blackwell, PTX 8.6)
#define FFMA2(acc, a, b) \
    asm("fma.rn.f32x2 %0, %1, %2, %3;" : "=l"(acc) : "l"(a), "l"(b), "l"(acc))
#define PACK2(out, lo, hi) \
    asm("mov.b64 %0, {%1, %2};" : "=l"(out) : "f"(lo), "f"(hi))

// ---------------------------------------------------------------------------
// init: deg = 1 (self loop) -- everything else initialized by later fusions
// ---------------------------------------------------------------------------
__global__ void k_init(int n) {
    int i = blockIdx.x * blockDim.x + threadIdx.x;
    if (i < n) g_deg[i] = 1.0f;
}

// ---------------------------------------------------------------------------
// GEMM1: h1 = x @ W1 + b1   (+ fused degree pass in epilogue)
// ---------------------------------------------------------------------------
#define GEMM1_SMEM ((NF * NH + 256 * 36) * sizeof(float))

__global__ void __launch_bounds__(256, 3) k_gemm1(const float* __restrict__ x,
                                                  const float* __restrict__ W1,
                                                  const float* __restrict__ b1,
                                                  const int* __restrict__ src,
                                                  int n, int E) {
    extern __shared__ float smem[];
    float* sW = smem;                 // NF*NH floats (32 KB)
    float* xt = smem + NF * NH;       // 256*36 floats (36 KB)
    int tid = threadIdx.x;
    int row0 = blockIdx.x * 256;
    int row = row0 + tid;

    {
        const float4* W4 = (const float4*)W1;
        float4* sW4 = (float4*)sW;
        for (int i = tid; i < NF * NH / 4; i += 256) sW4[i] = W4[i];
    }

    unsigned long long acc[8];
#pragma unroll
    for (int j = 0; j < 8; j++) {
        float lo = __ldg(&b1[2 * j]), hi = __ldg(&b1[2 * j + 1]);
        PACK2(acc[j], lo, hi);
    }

    const float4* xg = (const float4*)x;

    float4 pf[8];
#pragma unroll
    for (int q = 0; q < 8; q++) {
        int f = q * 256 + tid;
        int r = row0 + (f >> 3);
        int c4 = f & 7;
        pf[q] = (r < n) ? __ldg(&xg[(size_t)r * (NF / 4) + c4])
                        : make_float4(0.f, 0.f, 0.f, 0.f);
    }
    __syncthreads();

    for (int t = 0; t < NF / 32; t++) {
#pragma unroll
        for (int q = 0; q < 8; q++) {
            int f = q * 256 + tid;
            int r = f >> 3, c4 = f & 7;
            *(float4*)(&xt[r * 36 + c4 * 4]) = pf[q];
        }
        if (t + 1 < NF / 32) {
            int k0n = (t + 1) * 8;
#pragma unroll
            for (int q = 0; q < 8; q++) {
                int f = q * 256 + tid;
                int r = row0 + (f >> 3);
                int c4 = f & 7;
                pf[q] = (r < n) ? __ldg(&xg[(size_t)r * (NF / 4) + k0n + c4])
                                : make_float4(0.f, 0.f, 0.f, 0.f);
            }
        }
        __syncthreads();

        const ulonglong2* wk = (const ulonglong2*)(sW + (size_t)t * 32 * NH);
        const float* xr = &xt[tid * 36];
#pragma unroll
        for (int kq = 0; kq < 8; kq++) {
            float4 xv = *(const float4*)(xr + kq * 4);
#pragma unroll
            for (int j = 0; j < 4; j++) {
                int k = kq * 4 + j;
                float xs = (&xv.x)[j];
                unsigned long long xx;
                PACK2(xx, xs, xs);
                ulonglong2 wa = wk[k * 4 + 0];
                ulonglong2 wb = wk[k * 4 + 1];
                ulonglong2 wc = wk[k * 4 + 2];
                ulonglong2 wd = wk[k * 4 + 3];
                FFMA2(acc[0], xx, wa.x); FFMA2(acc[1], xx, wa.y);
                FFMA2(acc[2], xx, wb.x); FFMA2(acc[3], xx, wb.y);
                FFMA2(acc[4], xx, wc.x); FFMA2(acc[5], xx, wc.y);
                FFMA2(acc[6], xx, wd.x); FFMA2(acc[7], xx, wd.y);
            }
        }
        __syncthreads();
    }

    if (row < n) {
        unsigned long long* hr = (unsigned long long*)(g_h1 + (size_t)row * NH);
#pragma unroll
        for (int j = 0; j < 8; j++) hr[j] = acc[j];
    }

    // fused degree pass (grid-stride)
    int stride = gridDim.x * 256;
    for (int e = blockIdx.x * 256 + tid; e < E; e += stride)
        atomicAdd(&g_deg[src[e]], 1.0f);
}

// ---------------------------------------------------------------------------
// dinv + scale: h1s = dinv*h1 -> fp16 gather array; a1 init = fp32 self term
// ---------------------------------------------------------------------------
__global__ void k_dinv_scale(int n) {
    int r = blockIdx.x * blockDim.x + threadIdx.x;
    if (r >= n) return;
    float di = rsqrtf(g_deg[r]);
    g_dinv[r] = di;
    const float4* h = (const float4*)(g_h1 + (size_t)r * NH);
    float4* a = (float4*)(g_a1 + (size_t)r * NH);
    __half2 hh[8];
#pragma unroll
    for (int q = 0; q < 4; q++) {
        float4 v = h[q];
        float4 sv = make_float4(di * v.x, di * v.y, di * v.z, di * v.w);
        a[q] = sv;  // fp32 self term
        hh[2 * q + 0] = __floats2half2_rn(sv.x, sv.y);
        hh[2 * q + 1] = __floats2half2_rn(sv.z, sv.w);
    }
    uint4* dstp = (uint4*)(g_h1h + (size_t)r * NH);
    dstp[0] = *(uint4*)&hh[0];
    dstp[1] = *(uint4*)&hh[4];
}

// ---------------------------------------------------------------------------
// Aggregation layer 1: fp16 gather (8B/lane, 32B/edge) + fp32 float4 atomic
// ---------------------------------------------------------------------------
__global__ void k_agg1(const int* __restrict__ src,
                       const int* __restrict__ dst, int E) {
    int g = (blockIdx.x * blockDim.x + threadIdx.x) >> 2;
    int c4 = threadIdx.x & 3;
    if (g >= E) return;
    int s = src[g];
    int d = dst[g];
    uint2 raw = *(const uint2*)(g_h1h + (size_t)s * NH + c4 * 4);
    float2 f0 = __half22float2(*(__half2*)&raw.x);
    float2 f1 = __half22float2(*(__half2*)&raw.y);
    atomicAdd(((float4*)(g_a1 + (size_t)d * NH)) + c4,
              make_float4(f0.x, f0.y, f1.x, f1.y));
}

// a1s = dinv*relu(dinv*a1_total) -> fp16 gather array;
// agg2 init = fp32 self term; nsum init = dinv (self)
__global__ void k_post1(int n) {
    int r = blockIdx.x * blockDim.x + threadIdx.x;
    if (r >= n) return;
    float di = g_dinv[r];
    const float4* a = (const float4*)(g_a1 + (size_t)r * NH);
    float4* g2 = (float4*)(g_agg2 + (size_t)r * NH);
    __half2 hh[8];
#pragma unroll
    for (int q = 0; q < 4; q++) {
        float4 v = a[q];
        float4 sv = make_float4(di * fmaxf(di * v.x, 0.0f),
                                di * fmaxf(di * v.y, 0.0f),
                                di * fmaxf(di * v.z, 0.0f),
                                di * fmaxf(di * v.w, 0.0f));
        g2[q] = sv;  // fp32 self term
        hh[2 * q + 0] = __floats2half2_rn(sv.x, sv.y);
        hh[2 * q + 1] = __floats2half2_rn(sv.z, sv.w);
    }
    uint4* dstp = (uint4*)(g_a1sh + (size_t)r * NH);
    dstp[0] = *(uint4*)&hh[0];
    dstp[1] = *(uint4*)&hh[4];
    g_nsum[r] = di;  // self-loop bias weight
}

// ---------------------------------------------------------------------------
// Aggregation layer 2: fp16 gather + fp32 atomic; scalar dinv[s] for bias
// ---------------------------------------------------------------------------
__global__ void k_agg2(const int* __restrict__ src,
                       const int* __restrict__ dst, int E) {
    int g = (blockIdx.x * blockDim.x + threadIdx.x) >> 2;
    int c4 = threadIdx.x & 3;
    if (g >= E) return;
    int s = src[g];
    int d = dst[g];
    uint2 raw = *(const uint2*)(g_a1sh + (size_t)s * NH + c4 * 4);
    float2 f0 = __half22float2(*(__half2*)&raw.x);
    float2 f1 = __half22float2(*(__half2*)&raw.y);
    atomicAdd(((float4*)(g_agg2 + (size_t)d * NH)) + c4,
              make_float4(f0.x, f0.y, f1.x, f1.y));
    if (c4 == 0) atomicAdd(&g_nsum[d], g_dinv[s]);
}

// ---------------------------------------------------------------------------
// Fused: t = dinv*agg2_total;  ns = dinv*nsum_total
//        logits = ns*b2 + t@W2  ->  log_softmax  ->  out
// ---------------------------------------------------------------------------
__global__ void __launch_bounds__(128) k_final(const float* __restrict__ W2,
                                               const float* __restrict__ b2,
                                               float* __restrict__ out, int n) {
    __shared__ float sW[NH * NC];
    __shared__ float sb[NC];
    for (int i = threadIdx.x; i < NH * NC; i += blockDim.x) sW[i] = W2[i];
    if (threadIdx.x < NC) sb[threadIdx.x] = b2[threadIdx.x];
    __syncthreads();

    int r = blockIdx.x * blockDim.x + threadIdx.x;
    if (r >= n) return;

    float di = g_dinv[r];
    float ns = di * g_nsum[r];

    float tt[NH];
    const float4* ag = (const float4*)(g_agg2 + (size_t)r * NH);
#pragma unroll
    for (int q = 0; q < 4; q++) {
        float4 A = ag[q];
        tt[q * 4 + 0] = di * A.x;
        tt[q * 4 + 1] = di * A.y;
        tt[q * 4 + 2] = di * A.z;
        tt[q * 4 + 3] = di * A.w;
    }

    float v[NC];
#pragma unroll
    for (int c = 0; c < NC; c++) v[c] = ns * sb[c];
#pragma unroll
    for (int k = 0; k < NH; k++) {
        float tv = tt[k];
#pragma unroll
        for (int c = 0; c < NC; c++) v[c] += tv * sW[k * NC + c];
    }

    float m = v[0];
#pragma unroll
    for (int c = 1; c < NC; c++) m = fmaxf(m, v[c]);
    float s = 0.0f;
#pragma unroll
    for (int c = 0; c < NC; c++) s += expf(v[c] - m);
    float lse = m + logf(s);

    float4* orow = (float4*)(out + (size_t)r * NC);
#pragma unroll
    for (int q = 0; q < NC / 4; q++) {
        orow[q] = make_float4(v[q * 4 + 0] - lse, v[q * 4 + 1] - lse,
                              v[q * 4 + 2] - lse, v[q * 4 + 3] - lse);
    }
}

// ---------------------------------------------------------------------------
extern "C" void kernel_launch(void* const* d_in, const int* in_sizes, int n_in,
                              void* d_out, int out_size) {
    const float* x = (const float*)d_in[0];
    const int* ei = (const int*)d_in[1];     // int32 (JAX x64 disabled)
    const float* W1 = (const float*)d_in[2];
    const float* b1 = (const float*)d_in[3];
    const float* W2 = (const float*)d_in[4];
    const float* b2 = (const float*)d_in[5];
    float* out = (float*)d_out;

    int n = in_sizes[0] / NF;            // 100000
    int E = in_sizes[1] / 2;             // 3200000
    const int* src = ei;
    const int* dst = ei + E;

    cudaFuncSetAttribute(k_gemm1, cudaFuncAttributeMaxDynamicSharedMemorySize,
                         (int)GEMM1_SMEM);

    const int B = 256;
    k_init<<<(n + B - 1) / B, B>>>(n);
    k_gemm1<<<(n + 255) / 256, 256, GEMM1_SMEM>>>(x, W1, b1, src, n, E);
    k_dinv_scale<<<(n + B - 1) / B, B>>>(n);
    {
        long long th = (long long)E * 4;
        k_agg1<<<(unsigned)((th + B - 1) / B), B>>>(src, dst, E);
    }
    k_post1<<<(n + B - 1) / B, B>>>(n);
    {
        long long th = (long long)E * 4;
        k_agg2<<<(unsigned)((th + B - 1) / B), B>>>(src, dst, E);
    }
    k_final<<<(n + 127) / 128, 128>>>(W2, b2, out, n);
}

// round 11
// speedup vs baseline: 1.0006x; 1.0006x over previous
#include <cuda_runtime.h>
#include <cuda_fp16.h>

#define NF 512
#define NH 16
#define NC 40
#define NMAX 100000

// ---- scratch (static device globals; no allocations allowed) ----
__device__ float  g_deg[NMAX];
__device__ float  g_dinv[NMAX];
__device__ float  g_h1[NMAX * NH];    // x@W1+b1 (fp32, gemm output)
__device__ __half g_h1h[NMAX * NH];   // dinv*h1 in fp16 (gather source, 32B/row)
__device__ float  g_a1[NMAX * NH];    // layer-1 accumulator (init = dinv*h1 self term)
__device__ __half g_a1sh[NMAX * NH];  // dinv*relu(...) in fp16 (gather source)
__device__ float  g_agg2[NMAX * NH];  // layer-2 accumulator (init = a1s self term)
__device__ float  g_nsum[NMAX];       // bias weight accumulator (init = dinv self)

// packed fp32x2 FMA (Blackwell, PTX 8.6)
#define FFMA2(acc, a, b) \
    asm("fma.rn.f32x2 %0, %1, %2, %3;" : "=l"(acc) : "l"(a), "l"(b), "l"(acc))
#define PACK2(out, lo, hi) \
    asm("mov.b64 %0, {%1, %2};" : "=l"(out) : "f"(lo), "f"(hi))

// ---------------------------------------------------------------------------
// init: deg = 1 (self loop)
// ---------------------------------------------------------------------------
__global__ void k_init(int n) {
    int i = blockIdx.x * blockDim.x + threadIdx.x;
    if (i < n) g_deg[i] = 1.0f;
}

// ---------------------------------------------------------------------------
// GEMM1: h1 = x @ W1 + b1   (+ fused degree pass)
//  - 2 rows/thread (M-register-blocking): W broadcast LDS amortized over rows
//  - block 256 thr -> 512 rows; k-tile 16; xt pad 20 (odd float4 stride)
//  - smem 72KB -> 2 blocks/SM, grid 196, single wave
// ---------------------------------------------------------------------------
#define KT 16
#define BR 512
#define XPAD 20
#define GEMM1_SMEM ((NF * NH + BR * XPAD) * sizeof(float))

__global__ void __launch_bounds__(256, 2) k_gemm1(const float* __restrict__ x,
                                                  const float* __restrict__ W1,
                                                  const float* __restrict__ b1,
                                                  const int* __restrict__ src,
                                                  int n, int E) {
    extern __shared__ float smem[];
    float* sW = smem;                  // NF*NH floats (32 KB)
    float* xt = smem + NF * NH;        // BR*XPAD floats (40 KB)
    int tid = threadIdx.x;
    int row0 = blockIdx.x * BR;

    // load W1 into smem (coalesced float4)
    {
        const float4* W4 = (const float4*)W1;
        float4* sW4 = (float4*)sW;
        for (int i = tid; i < NF * NH / 4; i += 256) sW4[i] = W4[i];
    }

    // packed accumulators for 2 rows, init from bias
    unsigned long long acc0[8], acc1[8];
#pragma unroll
    for (int j = 0; j < 8; j++) {
        float lo = __ldg(&b1[2 * j]), hi = __ldg(&b1[2 * j + 1]);
        PACK2(acc0[j], lo, hi);
        acc1[j] = acc0[j];
    }

    const float4* xg = (const float4*)x;

    // prefetch tile 0: 512 rows x 16 cols = 2048 float4, 8 per thread
    float4 pf[8];
#pragma unroll
    for (int q = 0; q < 8; q++) {
        int f = q * 256 + tid;
        int r = row0 + (f >> 2);
        int c4 = f & 3;
        pf[q] = (r < n) ? __ldg(&xg[(size_t)r * (NF / 4) + c4])
                        : make_float4(0.f, 0.f, 0.f, 0.f);
    }
    __syncthreads();  // sW ready

    for (int t = 0; t < NF / KT; t++) {
        // STS.128 tile store
#pragma unroll
        for (int q = 0; q < 8; q++) {
            int f = q * 256 + tid;
            int r = f >> 2, c4 = f & 3;
            *(float4*)(&xt[r * XPAD + c4 * 4]) = pf[q];
        }
        // prefetch next tile
        if (t + 1 < NF / KT) {
            int k0n = (t + 1) * (KT / 4);
#pragma unroll
            for (int q = 0; q < 8; q++) {
                int f = q * 256 + tid;
                int r = row0 + (f >> 2);
                int c4 = f & 3;
                pf[q] = (r < n) ? __ldg(&xg[(size_t)r * (NF / 4) + k0n + c4])
                                : make_float4(0.f, 0.f, 0.f, 0.f);
            }
        }
        __syncthreads();  // tile t visible

        const ulonglong2* wk = (const ulonglong2*)(sW + (size_t)t * KT * NH);
        const float* xr0 = &xt[tid * XPAD];
        const float* xr1 = &xt[(tid + 256) * XPAD];
#pragma unroll
        for (int kq = 0; kq < KT / 4; kq++) {
            float4 xv0 = *(const float4*)(xr0 + kq * 4);  // LDS.128, odd stride
            float4 xv1 = *(const float4*)(xr1 + kq * 4);
#pragma unroll
            for (int j = 0; j < 4; j++) {
                int k = kq * 4 + j;
                unsigned long long xx0, xx1;
                float s0 = (&xv0.x)[j], s1 = (&xv1.x)[j];
                PACK2(xx0, s0, s0);
                PACK2(xx1, s1, s1);
                ulonglong2 wa = wk[k * 4 + 0];  // W loaded ONCE for both rows
                ulonglong2 wb = wk[k * 4 + 1];
                ulonglong2 wc = wk[k * 4 + 2];
                ulonglong2 wd = wk[k * 4 + 3];
                FFMA2(acc0[0], xx0, wa.x); FFMA2(acc0[1], xx0, wa.y);
                FFMA2(acc0[2], xx0, wb.x); FFMA2(acc0[3], xx0, wb.y);
                FFMA2(acc0[4], xx0, wc.x); FFMA2(acc0[5], xx0, wc.y);
                FFMA2(acc0[6], xx0, wd.x); FFMA2(acc0[7], xx0, wd.y);
                FFMA2(acc1[0], xx1, wa.x); FFMA2(acc1[1], xx1, wa.y);
                FFMA2(acc1[2], xx1, wb.x); FFMA2(acc1[3], xx1, wb.y);
                FFMA2(acc1[4], xx1, wc.x); FFMA2(acc1[5], xx1, wc.y);
                FFMA2(acc1[6], xx1, wd.x); FFMA2(acc1[7], xx1, wd.y);
            }
        }
        __syncthreads();  // done reading xt
    }

    int rA = row0 + tid, rB = row0 + tid + 256;
    if (rA < n) {
        unsigned long long* hr = (unsigned long long*)(g_h1 + (size_t)rA * NH);
#pragma unroll
        for (int j = 0; j < 8; j++) hr[j] = acc0[j];
    }
    if (rB < n) {
        unsigned long long* hr = (unsigned long long*)(g_h1 + (size_t)rB * NH);
#pragma unroll
        for (int j = 0; j < 8; j++) hr[j] = acc1[j];
    }

    // fused degree pass (grid-stride)
    int stride = gridDim.x * 256;
    for (int e = blockIdx.x * 256 + tid; e < E; e += stride)
        atomicAdd(&g_deg[src[e]], 1.0f);
}

// ---------------------------------------------------------------------------
// dinv + scale: h1s = dinv*h1 -> fp16 gather array; a1 init = fp32 self term
// ---------------------------------------------------------------------------
__global__ void k_dinv_scale(int n) {
    int r = blockIdx.x * blockDim.x + threadIdx.x;
    if (r >= n) return;
    float di = rsqrtf(g_deg[r]);
    g_dinv[r] = di;
    const float4* h = (const float4*)(g_h1 + (size_t)r * NH);
    float4* a = (float4*)(g_a1 + (size_t)r * NH);
    __half2 hh[8];
#pragma unroll
    for (int q = 0; q < 4; q++) {
        float4 v = h[q];
        float4 sv = make_float4(di * v.x, di * v.y, di * v.z, di * v.w);
        a[q] = sv;  // fp32 self term
        hh[2 * q + 0] = __floats2half2_rn(sv.x, sv.y);
        hh[2 * q + 1] = __floats2half2_rn(sv.z, sv.w);
    }
    uint4* dstp = (uint4*)(g_h1h + (size_t)r * NH);
    dstp[0] = *(uint4*)&hh[0];
    dstp[1] = *(uint4*)&hh[4];
}

// ---------------------------------------------------------------------------
// Aggregation layer 1: fp16 gather + fp32 float4 atomic
// ---------------------------------------------------------------------------
__global__ void k_agg1(const int* __restrict__ src,
                       const int* __restrict__ dst, int E) {
    int g = (blockIdx.x * blockDim.x + threadIdx.x) >> 2;
    int c4 = threadIdx.x & 3;
    if (g >= E) return;
    int s = src[g];
    int d = dst[g];
    uint2 raw = *(const uint2*)(g_h1h + (size_t)s * NH + c4 * 4);
    float2 f0 = __half22float2(*(__half2*)&raw.x);
    float2 f1 = __half22float2(*(__half2*)&raw.y);
    atomicAdd(((float4*)(g_a1 + (size_t)d * NH)) + c4,
              make_float4(f0.x, f0.y, f1.x, f1.y));
}

// a1s = dinv*relu(dinv*a1_total) -> fp16; agg2 init = fp32 self; nsum = dinv
__global__ void k_post1(int n) {
    int r = blockIdx.x * blockDim.x + threadIdx.x;
    if (r >= n) return;
    float di = g_dinv[r];
    const float4* a = (const float4*)(g_a1 + (size_t)r * NH);
    float4* g2 = (float4*)(g_agg2 + (size_t)r * NH);
    __half2 hh[8];
#pragma unroll
    for (int q = 0; q < 4; q++) {
        float4 v = a[q];
        float4 sv = make_float4(di * fmaxf(di * v.x, 0.0f),
                                di * fmaxf(di * v.y, 0.0f),
                                di * fmaxf(di * v.z, 0.0f),
                                di * fmaxf(di * v.w, 0.0f));
        g2[q] = sv;  // fp32 self term
        hh[2 * q + 0] = __floats2half2_rn(sv.x, sv.y);
        hh[2 * q + 1] = __floats2half2_rn(sv.z, sv.w);
    }
    uint4* dstp = (uint4*)(g_a1sh + (size_t)r * NH);
    dstp[0] = *(uint4*)&hh[0];
    dstp[1] = *(uint4*)&hh[4];
    g_nsum[r] = di;  // self-loop bias weight
}

// ---------------------------------------------------------------------------
// Aggregation layer 2: fp16 gather + fp32 atomic; scalar dinv[s] for bias
// ---------------------------------------------------------------------------
__global__ void k_agg2(const int* __restrict__ src,
                       const int* __restrict__ dst, int E) {
    int g = (blockIdx.x * blockDim.x + threadIdx.x) >> 2;
    int c4 = threadIdx.x & 3;
    if (g >= E) return;
    int s = src[g];
    int d = dst[g];
    uint2 raw = *(const uint2*)(g_a1sh + (size_t)s * NH + c4 * 4);
    float2 f0 = __half22float2(*(__half2*)&raw.x);
    float2 f1 = __half22float2(*(__half2*)&raw.y);
    atomicAdd(((float4*)(g_agg2 + (size_t)d * NH)) + c4,
              make_float4(f0.x, f0.y, f1.x, f1.y));
    if (c4 == 0) atomicAdd(&g_nsum[d], g_dinv[s]);
}

// ---------------------------------------------------------------------------
// Fused: t = dinv*agg2_total;  ns = dinv*nsum_total
//        logits = ns*b2 + t@W2  ->  log_softmax  ->  out
// ---------------------------------------------------------------------------
__global__ void __launch_bounds__(128) k_final(const float* __restrict__ W2,
                                               const float* __restrict__ b2,
                                               float* __restrict__ out, int n) {
    __shared__ float sW[NH * NC];
    __shared__ float sb[NC];
    for (int i = threadIdx.x; i < NH * NC; i += blockDim.x) sW[i] = W2[i];
    if (threadIdx.x < NC) sb[threadIdx.x] = b2[threadIdx.x];
    __syncthreads();

    int r = blockIdx.x * blockDim.x + threadIdx.x;
    if (r >= n) return;

    float di = g_dinv[r];
    float ns = di * g_nsum[r];

    float tt[NH];
    const float4* ag = (const float4*)(g_agg2 + (size_t)r * NH);
#pragma unroll
    for (int q = 0; q < 4; q++) {
        float4 A = ag[q];
        tt[q * 4 + 0] = di * A.x;
        tt[q * 4 + 1] = di * A.y;
        tt[q * 4 + 2] = di * A.z;
        tt[q * 4 + 3] = di * A.w;
    }

    float v[NC];
#pragma unroll
    for (int c = 0; c < NC; c++) v[c] = ns * sb[c];
#pragma unroll
    for (int k = 0; k < NH; k++) {
        float tv = tt[k];
#pragma unroll
        for (int c = 0; c < NC; c++) v[c] += tv * sW[k * NC + c];
    }

    float m = v[0];
#pragma unroll
    for (int c = 1; c < NC; c++) m = fmaxf(m, v[c]);
    float s = 0.0f;
#pragma unroll
    for (int c = 0; c < NC; c++) s += expf(v[c] - m);
    float lse = m + logf(s);

    float4* orow = (float4*)(out + (size_t)r * NC);
#pragma unroll
    for (int q = 0; q < NC / 4; q++) {
        orow[q] = make_float4(v[q * 4 + 0] - lse, v[q * 4 + 1] - lse,
                              v[q * 4 + 2] - lse, v[q * 4 + 3] - lse);
    }
}

// ---------------------------------------------------------------------------
extern "C" void kernel_launch(void* const* d_in, const int* in_sizes, int n_in,
                              void* d_out, int out_size) {
    const float* x = (const float*)d_in[0];
    const int* ei = (const int*)d_in[1];     // int32 (JAX x64 disabled)
    const float* W1 = (const float*)d_in[2];
    const float* b1 = (const float*)d_in[3];
    const float* W2 = (const float*)d_in[4];
    const float* b2 = (const float*)d_in[5];
    float* out = (float*)d_out;

    int n = in_sizes[0] / NF;            // 100000
    int E = in_sizes[1] / 2;             // 3200000
    const int* src = ei;
    const int* dst = ei + E;

    cudaFuncSetAttribute(k_gemm1, cudaFuncAttributeMaxDynamicSharedMemorySize,
                         (int)GEMM1_SMEM);

    const int B = 256;
    k_init<<<(n + B - 1) / B, B>>>(n);
    k_gemm1<<<(n + BR - 1) / BR, 256, GEMM1_SMEM>>>(x, W1, b1, src, n, E);
    k_dinv_scale<<<(n + B - 1) / B, B>>>(n);
    {
        long long th = (long long)E * 4;
        k_agg1<<<(unsigned)((th + B - 1) / B), B>>>(src, dst, E);
    }
    k_post1<<<(n + B - 1) / B, B>>>(n);
    {
        long long th = (long long)E * 4;
        k_agg2<<<(unsigned)((th + B - 1) / B), B>>>(src, dst, E);
    }
    k_final<<<(n + 127) / 128, 128>>>(W2, b2, out, n);
}